// round 9
// baseline (speedup 1.0000x reference)
#include <cuda_runtime.h>

// FFT_19490561589800: batch of 16384 x 1024-point FFT of real input.
// Output: [real plane (16384x1024), imag plane (16384x1024)] fp32.
//
// Four-step FFT, 1024 = 32 x 32; one warp per TWO real rows packed as one
// complex FFT (Hermitian trick). R4 structure (shared transpose + scalar
// shared epilogue, no cache hints) at 6 blocks/SM: output addressing deferred
// to the epilogue and dual-chain twiddle recurrence keep regs <= ~80.

static constexpr int N = 1024;

// 5-bit bit reversal; folds to an immediate at every unrolled call site.
__device__ __host__ constexpr int br5(int i){
    return ((i & 1) << 4) | ((i & 2) << 2) | (i & 4) | ((i & 8) >> 2) | ((i & 16) >> 4);
}

__device__ __forceinline__ float2 cmulf(float2 a, float2 b){
    return make_float2(fmaf(a.x, b.x, -(a.y * b.y)),
                       fmaf(a.x, b.y,  (a.y * b.x)));
}

// One DIF radix-2 stage of an in-register 32-point FFT.
template<int LEN>
__device__ __forceinline__ void fft32_stage(float2* v){
    constexpr int HALF = LEN / 2;
    constexpr int TS   = 32 / LEN;
    constexpr float C[16] = {
        1.0f,                 0.98078528040323044f, 0.92387953251128674f, 0.83146961230254524f,
        0.70710678118654752f, 0.55557023301960222f, 0.38268343236508977f, 0.19509032201612825f,
        0.0f,                -0.19509032201612825f,-0.38268343236508977f,-0.55557023301960222f,
       -0.70710678118654752f,-0.83146961230254524f,-0.92387953251128674f,-0.98078528040323044f};
    constexpr float S[16] = {
        0.0f,                -0.19509032201612825f,-0.38268343236508977f,-0.55557023301960222f,
       -0.70710678118654752f,-0.83146961230254524f,-0.92387953251128674f,-0.98078528040323044f,
       -1.0f,                -0.98078528040323044f,-0.92387953251128674f,-0.83146961230254524f,
       -0.70710678118654752f,-0.55557023301960222f,-0.38268343236508977f,-0.19509032201612825f};
#pragma unroll
    for (int base = 0; base < 32; base += LEN){
#pragma unroll
        for (int j = 0; j < HALF; j++){
            float2 a = v[base + j];
            float2 b = v[base + j + HALF];
            float2 s = make_float2(a.x + b.x, a.y + b.y);
            float2 d = make_float2(a.x - b.x, a.y - b.y);
            const int tj = j * TS;   // compile-time after unroll
            float2 r;
            if      (tj == 0) r = d;
            else if (tj == 8) r = make_float2(d.y, -d.x);             // * (-i)
            else              r = make_float2(d.x*C[tj] - d.y*S[tj],
                                              d.x*S[tj] + d.y*C[tj]);
            v[base + j]        = s;
            v[base + j + HALF] = r;
        }
    }
}

// Natural-order input, bit-reversed output: after call, v[i] = X[br5(i)]
__device__ __forceinline__ void fft32(float2* v){
    fft32_stage<32>(v);
    fft32_stage<16>(v);
    fft32_stage<8>(v);
    fft32_stage<4>(v);
    fft32_stage<2>(v);
}

#define PAIRS_PER_BLOCK 4
#define THREADS 128

__global__ void __launch_bounds__(THREADS, 6)
fft_kernel(const float* __restrict__ x,
           const float* __restrict__ twr,   // tw_real_3: cos(2*pi*j/1024), j<512
           const float* __restrict__ twi,   // tw_imag_3: -sin(2*pi*j/1024)
           float* __restrict__ out,
           int n_rows)
{
    // per-warp transpose buffers: 32x32 with pad 33 (conflict-free both phases)
    __shared__ float s_re[PAIRS_PER_BLOCK][33 * 32];
    __shared__ float s_im[PAIRS_PER_BLOCK][33 * 32];

    const int t = threadIdx.x & 31;    // lane
    const int w = threadIdx.x >> 5;    // warp in block = pair in block
    const int pair = blockIdx.x * PAIRS_PER_BLOCK + w;
    if (pair * 2 + 1 >= n_rows) return;

    const float* xa = x + (size_t)(pair * 2) * N;
    float* sre = s_re[w];
    float* sim = s_im[w];

    // ---- load: z[n] = xa[n] + i*xb[n]; thread t owns n2 = t, n = 32*n1 + t ----
    float2 v[32];
#pragma unroll
    for (int n1 = 0; n1 < 32; n1++){
        v[n1].x = xa[32 * n1 + t];
        v[n1].y = xa[N + 32 * n1 + t];
    }

    // ---- stage A: 32-pt FFT over n1 ----
    fft32(v);                       // v[i] = A[br5(i)]

    // ---- inter-stage twiddle: A[k1] *= W_1024^{t*k1} ----
    // Two interleaved recurrences (step base^2) to halve the dependency chain.
    {
        const float2 b1 = make_float2(twr[t], twi[t]);   // W_1024^t
        const float2 b2 = cmulf(b1, b1);                 // W_1024^{2t}
        float2 cur_o = b1;   // k1 = 1, 3, 5, ...
        float2 cur_e = b2;   // k1 = 2, 4, 6, ...
#pragma unroll
        for (int k1 = 1; k1 < 32; k1 += 2){
            v[br5(k1)] = cmulf(v[br5(k1)], cur_o);
            cur_o = cmulf(cur_o, b2);
        }
#pragma unroll
        for (int k1 = 2; k1 < 32; k1 += 2){
            v[br5(k1)] = cmulf(v[br5(k1)], cur_e);
            cur_e = cmulf(cur_e, b2);
        }
    }

    // ---- transpose via shared: (k1, n2=t) -> thread t becomes k1 ----
#pragma unroll
    for (int i = 0; i < 32; i++){
        const int k1 = br5(i);
        sre[k1 * 33 + t] = v[i].x;
        sim[k1 * 33 + t] = v[i].y;
    }
    __syncwarp();
#pragma unroll
    for (int n2 = 0; n2 < 32; n2++){
        v[n2].x = sre[t * 33 + n2];
        v[n2].y = sim[t * 33 + n2];
    }
    __syncwarp();   // WAR: everyone done reading before buffer reuse below

    // ---- stage B: 32-pt FFT over n2 ----
    fft32(v);                       // v[i] = Z[t + 32*br5(i)]

    // ---- store Z to shared in natural order k = t + 32*k2 ----
#pragma unroll
    for (int i = 0; i < 32; i++){
        const int k2 = br5(i);
        sre[t + 32 * k2] = v[i].x;
        sim[t + 32 * k2] = v[i].y;
    }
    __syncwarp();

    // ---- Hermitian unpack: two real-row spectra from one complex FFT ----
    // Output addressing recomputed here (keeps register pressure off the FFT).
    const size_t IMOFF = (size_t)n_rows * N;
    float* oar = out + (size_t)(pair * 2) * N;
    float* oai = oar + IMOFF;
    float* obr = oar + N;
    float* obi = obr + IMOFF;
#pragma unroll
    for (int k2 = 0; k2 < 32; k2++){
        const int k = t + 32 * k2;
        const int m = (N - k) & (N - 1);
        const float zr = sre[k], zi = sim[k];
        const float wr = sre[m], wi = sim[m];
        oar[k] = 0.5f * (zr + wr);
        oai[k] = 0.5f * (zi - wi);
        obr[k] = 0.5f * (zi + wi);
        obi[k] = 0.5f * (wr - zr);
    }
}

extern "C" void kernel_launch(void* const* d_in, const int* in_sizes, int n_in,
                              void* d_out, int out_size)
{
    const float* x   = (const float*)d_in[0];
    const float* twr = (const float*)d_in[10];   // tw_real_3 (512: W_1024^j)
    const float* twi = (const float*)d_in[11];   // tw_imag_3
    float* out = (float*)d_out;

    const int n_rows = in_sizes[0] / N;          // 16384
    const int pairs  = n_rows / 2;               // 8192
    const int blocks = (pairs + PAIRS_PER_BLOCK - 1) / PAIRS_PER_BLOCK;  // 2048

    fft_kernel<<<blocks, THREADS>>>(x, twr, twi, out, n_rows);
}

// round 10
// speedup vs baseline: 1.0685x; 1.0685x over previous
#include <cuda_runtime.h>

// FFT_19490561589800: batch of 16384 x 1024-point FFT of real input.
// Output: [real plane (16384x1024), imag plane (16384x1024)] fp32.
//
// Four-step FFT, 1024 = 32 x 32; one warp per TWO real rows packed as one
// complex FFT (Hermitian trick). Complex values live in packed b64 registers
// and butterflies use Blackwell f32x2 packed math (add/sub/mul/fma.rn.f32x2,
// PTX-only) to halve the fp instruction count of the butterfly adds.
// The epilogue 0.5 scale is folded into a packed input prescale (linearity).

static constexpr int N = 1024;

// 5-bit bit reversal; folds to an immediate at every unrolled call site.
__device__ __host__ constexpr int br5(int i){
    return ((i & 1) << 4) | ((i & 2) << 2) | (i & 4) | ((i & 8) >> 2) | ((i & 16) >> 4);
}

// ---------- packed complex: (re = lo 32 bits, im = hi 32 bits) ----------
typedef unsigned long long cplx;

__device__ __host__ constexpr cplx packc(float lo, float hi){
    return (cplx)__builtin_bit_cast(unsigned int, lo)
         | ((cplx)__builtin_bit_cast(unsigned int, hi) << 32);
}

__device__ __forceinline__ cplx cpack(float x, float y){
    cplx r; asm("mov.b64 %0, {%1, %2};" : "=l"(r) : "f"(x), "f"(y)); return r;
}
__device__ __forceinline__ float2 cunpack(cplx a){
    float2 f; asm("mov.b64 {%0, %1}, %2;" : "=f"(f.x), "=f"(f.y) : "l"(a)); return f;
}
__device__ __forceinline__ cplx cadd(cplx a, cplx b){
    cplx r; asm("add.rn.f32x2 %0, %1, %2;" : "=l"(r) : "l"(a), "l"(b)); return r;
}
__device__ __forceinline__ cplx csub(cplx a, cplx b){
    cplx r; asm("sub.rn.f32x2 %0, %1, %2;" : "=l"(r) : "l"(a), "l"(b)); return r;
}
__device__ __forceinline__ cplx cmulel(cplx a, cplx b){   // elementwise
    cplx r; asm("mul.rn.f32x2 %0, %1, %2;" : "=l"(r) : "l"(a), "l"(b)); return r;
}
// r = d * (c + i*s), cc = (c,c), ss = (-s,s):  r = d*cc + swap(d)*ss
__device__ __forceinline__ cplx ctw(cplx d, cplx cc, cplx ss){
    float2 fd = cunpack(d);
    cplx dsw = cpack(fd.y, fd.x);
    cplx t, r;
    asm("mul.rn.f32x2 %0, %1, %2;" : "=l"(t) : "l"(dsw), "l"(ss));
    asm("fma.rn.f32x2 %0, %1, %2, %3;" : "=l"(r) : "l"(d), "l"(cc), "l"(t));
    return r;
}

__device__ __forceinline__ float2 cmulf(float2 a, float2 b){
    return make_float2(fmaf(a.x, b.x, -(a.y * b.y)),
                       fmaf(a.x, b.y,  (a.y * b.x)));
}

// One DIF radix-2 stage of an in-register 32-point FFT (packed math).
template<int LEN>
__device__ __forceinline__ void fft32_stage(cplx* v){
    constexpr int HALF = LEN / 2;
    constexpr int TS   = 32 / LEN;
    constexpr float C[16] = {
        1.0f,                 0.98078528040323044f, 0.92387953251128674f, 0.83146961230254524f,
        0.70710678118654752f, 0.55557023301960222f, 0.38268343236508977f, 0.19509032201612825f,
        0.0f,                -0.19509032201612825f,-0.38268343236508977f,-0.55557023301960222f,
       -0.70710678118654752f,-0.83146961230254524f,-0.92387953251128674f,-0.98078528040323044f};
    constexpr float S[16] = {
        0.0f,                -0.19509032201612825f,-0.38268343236508977f,-0.55557023301960222f,
       -0.70710678118654752f,-0.83146961230254524f,-0.92387953251128674f,-0.98078528040323044f,
       -1.0f,                -0.98078528040323044f,-0.92387953251128674f,-0.83146961230254524f,
       -0.70710678118654752f,-0.55557023301960222f,-0.38268343236508977f,-0.19509032201612825f};
#pragma unroll
    for (int base = 0; base < 32; base += LEN){
#pragma unroll
        for (int j = 0; j < HALF; j++){
            cplx a = v[base + j];
            cplx b = v[base + j + HALF];
            cplx s = cadd(a, b);
            cplx d = csub(a, b);
            const int tj = j * TS;   // compile-time after unroll
            cplx r;
            if (tj == 0){
                r = d;
            } else if (tj == 8){                     // * (-i)
                float2 fd = cunpack(d);
                r = cpack(fd.y, -fd.x);
            } else {
                r = ctw(d, packc(C[tj], C[tj]), packc(-S[tj], S[tj]));
            }
            v[base + j]        = s;
            v[base + j + HALF] = r;
        }
    }
}

// Natural-order input, bit-reversed output: after call, v[i] = X[br5(i)]
__device__ __forceinline__ void fft32(cplx* v){
    fft32_stage<32>(v);
    fft32_stage<16>(v);
    fft32_stage<8>(v);
    fft32_stage<4>(v);
    fft32_stage<2>(v);
}

#define PAIRS_PER_BLOCK 4
#define THREADS 128

__global__ void __launch_bounds__(THREADS, 4)
fft_kernel(const float* __restrict__ x,
           const float* __restrict__ twr,   // tw_real_3: cos(2*pi*j/1024), j<512
           const float* __restrict__ twi,   // tw_imag_3: -sin(2*pi*j/1024)
           float* __restrict__ out,
           int n_rows)
{
    // per-warp transpose buffers: 32x32 with pad 33 (conflict-free both phases)
    __shared__ float s_re[PAIRS_PER_BLOCK][33 * 32];
    __shared__ float s_im[PAIRS_PER_BLOCK][33 * 32];

    const int t = threadIdx.x & 31;    // lane
    const int w = threadIdx.x >> 5;    // warp in block = pair in block
    const int pair = blockIdx.x * PAIRS_PER_BLOCK + w;
    const int rowa = pair * 2;
    const int rowb = rowa + 1;
    if (rowb >= n_rows) return;

    const size_t IMOFF = (size_t)n_rows * N;   // offset of imag plane in out

    const float* xa = x + (size_t)rowa * N;
    const float* xb = x + (size_t)rowb * N;
    float* sre = s_re[w];
    float* sim = s_im[w];

    // ---- load: z[n] = 0.5*(xa[n] + i*xb[n]); prescale folds the Hermitian
    //      epilogue's 0.5 factor into the (linear) FFT input ----
    cplx v[32];
#pragma unroll
    for (int n1 = 0; n1 < 32; n1++){
        v[n1] = cmulel(cpack(xa[32 * n1 + t], xb[32 * n1 + t]),
                       packc(0.5f, 0.5f));
    }

    // ---- stage A: 32-pt FFT over n1 ----
    fft32(v);                       // v[i] = A[br5(i)]

    // ---- inter-stage twiddle: A[k1] *= W_1024^{t*k1} ----
    // Two interleaved recurrences (step base^2) to halve the dependency chain.
    {
        const float2 b1 = make_float2(twr[t], twi[t]);   // W_1024^t
        const float2 b2 = cmulf(b1, b1);                 // W_1024^{2t}
        float2 cur_o = b1;   // k1 = 1, 3, 5, ...
        float2 cur_e = b2;   // k1 = 2, 4, 6, ...
#pragma unroll
        for (int k1 = 1; k1 < 32; k1 += 2){
            float2 f = cmulf(cunpack(v[br5(k1)]), cur_o);
            v[br5(k1)] = cpack(f.x, f.y);
            cur_o = cmulf(cur_o, b2);
        }
#pragma unroll
        for (int k1 = 2; k1 < 32; k1 += 2){
            float2 f = cmulf(cunpack(v[br5(k1)]), cur_e);
            v[br5(k1)] = cpack(f.x, f.y);
            cur_e = cmulf(cur_e, b2);
        }
    }

    // ---- transpose via shared: (k1, n2=t) -> thread t becomes k1 ----
#pragma unroll
    for (int i = 0; i < 32; i++){
        const int k1 = br5(i);
        const float2 f = cunpack(v[i]);
        sre[k1 * 33 + t] = f.x;
        sim[k1 * 33 + t] = f.y;
    }
    __syncwarp();
#pragma unroll
    for (int n2 = 0; n2 < 32; n2++){
        v[n2] = cpack(sre[t * 33 + n2], sim[t * 33 + n2]);
    }
    __syncwarp();   // WAR: everyone done reading before buffer reuse below

    // ---- stage B: 32-pt FFT over n2 ----
    fft32(v);                       // v[i] = Z[t + 32*br5(i)]  (prescaled by 0.5)

    // ---- store Z to shared in natural order k = t + 32*k2 ----
#pragma unroll
    for (int i = 0; i < 32; i++){
        const int k2 = br5(i);
        const float2 f = cunpack(v[i]);
        sre[t + 32 * k2] = f.x;
        sim[t + 32 * k2] = f.y;
    }
    __syncwarp();

    // ---- Hermitian unpack (Z already carries the 0.5 factor) ----
    float* oar = out + (size_t)rowa * N;
    float* oai = oar + IMOFF;
    float* obr = out + (size_t)rowb * N;
    float* obi = obr + IMOFF;
#pragma unroll
    for (int k2 = 0; k2 < 32; k2++){
        const int k = t + 32 * k2;
        const int m = (N - k) & (N - 1);
        const float zr = sre[k], zi = sim[k];
        const float wr = sre[m], wi = sim[m];
        oar[k] = zr + wr;
        oai[k] = zi - wi;
        obr[k] = zi + wi;
        obi[k] = wr - zr;
    }
}

extern "C" void kernel_launch(void* const* d_in, const int* in_sizes, int n_in,
                              void* d_out, int out_size)
{
    const float* x   = (const float*)d_in[0];
    const float* twr = (const float*)d_in[10];   // tw_real_3 (512: W_1024^j)
    const float* twi = (const float*)d_in[11];   // tw_imag_3
    float* out = (float*)d_out;

    const int n_rows = in_sizes[0] / N;          // 16384
    const int pairs  = n_rows / 2;               // 8192
    const int blocks = (pairs + PAIRS_PER_BLOCK - 1) / PAIRS_PER_BLOCK;  // 2048

    fft_kernel<<<blocks, THREADS>>>(x, twr, twi, out, n_rows);
}